// round 16
// baseline (speedup 1.0000x reference)
#include <cuda_runtime.h>
#include <cuda_fp16.h>
#include <float.h>

#define NIMG 32
#define H    512
#define W    512
#define HW   (H * W)
#define CHW  (3 * HW)

#define NEG2 0xFC00FC00u      // half2(-inf, -inf)

#define VBLK  (NIMG * 16 * 2)        // 1024 blocks: (img, 32-row strip, col half)

__device__ __half g_hmax[NIMG * HW]; // fp16 intermediate (16.75 MB, L2-resident)
__device__ float  g_partial[VBLK];
__device__ int    g_count;           // zero-init; reset by last block

__device__ __forceinline__ unsigned hmax2u(unsigned a, unsigned b) {
    __half2 ha = *reinterpret_cast<__half2*>(&a);
    __half2 hb = *reinterpret_cast<__half2*>(&b);
    __half2 hm = __hmax2(ha, hb);
    return *reinterpret_cast<unsigned*>(&hm);
}
__device__ __forceinline__ unsigned sh1(unsigned a, unsigned b) {
    return __byte_perm(a, b, 0x5432);   // (a.hi, b.lo)
}

// ---------------------------------------------------------------------------
// Kernel 1 — EXACT R13 version (measured best; ~17us, at LTS cap):
// c = 1 - min3(channels) -> fp16, horizontal 35-wide sliding max, packed half2.
// One block per (n,h) row, 128 threads.
// ---------------------------------------------------------------------------
__global__ __launch_bounds__(128) void hpass_kernel(const float* __restrict__ img) {
    const int row = blockIdx.x;
    const int n   = row >> 9;
    const int h   = row & (H - 1);
    const float* p = img + (size_t)n * CHW + (size_t)h * W;

    __shared__ unsigned s2[276];   // px -20 .. 531
    __shared__ unsigned t2[276];

    const int tid = threadIdx.x;

    if (tid < 20) s2[tid < 10 ? tid : 256 + tid] = NEG2;

    const float4 a = ((const float4*)p)[tid];
    const float4 b = ((const float4*)(p + HW))[tid];
    const float4 c = ((const float4*)(p + 2 * HW))[tid];
    float c0 = 1.0f - fminf(a.x, fminf(b.x, c.x));
    float c1 = 1.0f - fminf(a.y, fminf(b.y, c.y));
    float c2 = 1.0f - fminf(a.z, fminf(b.z, c.z));
    float c3 = 1.0f - fminf(a.w, fminf(b.w, c.w));
    __half2 h01 = __floats2half2_rn(c0, c1);
    __half2 h23 = __floats2half2_rn(c2, c3);
    s2[2 * tid + 10] = *reinterpret_cast<unsigned*>(&h01);
    s2[2 * tid + 11] = *reinterpret_cast<unsigned*>(&h23);
    __syncthreads();

    #pragma unroll
    for (int i = tid; i < 273; i += 128) {
        const unsigned A = s2[i], B = s2[i + 1], C = s2[i + 2];
        t2[i] = hmax2u(hmax2u(hmax2u(A, sh1(A, B)), hmax2u(B, sh1(B, C))), C);
    }
    __syncthreads();

    unsigned* orow = (unsigned*)(g_hmax + (size_t)row * W);
    #pragma unroll
    for (int q = tid; q < 256; q += 128) {
        unsigned v;
        v = sh1(t2[q + 1], t2[q + 2]);
        v = hmax2u(v, t2[q + 4]);
        v = hmax2u(v, sh1(t2[q + 6], t2[q + 7]));
        v = hmax2u(v, t2[q + 9]);
        v = hmax2u(v, sh1(t2[q + 11], t2[q + 12]));
        v = hmax2u(v, t2[q + 14]);
        v = hmax2u(v, sh1(t2[q + 16], t2[q + 17]));
        orow[q] = v;
    }
}

// ---------------------------------------------------------------------------
// Per-thread vertical 35-max column scan over a 32-row strip (R13 internals,
// register-resident tb ring). width-35 = 5 taps (stride 7) over width-7
// brick maxes; ring tb[5][7]. CLAMP=false for the 14/16 interior strips.
// ---------------------------------------------------------------------------
template <bool CLAMP>
__device__ __forceinline__ float vcol_scan(const unsigned* __restrict__ base,
                                           int rbase, int col) {
    unsigned s[13];
    unsigned tb[5][7];
    float acc = 0.0f;

    #pragma unroll
    for (int i = 0; i < 13; i++) {
        const int row = CLAMP ? min(max(rbase + i, 0), H - 1) : (rbase + i);
        s[i] = base[row * 256 + col];
    }

    #pragma unroll
    for (int c = 0; c < 9; c++) {
        const unsigned pre5 = hmax2u(s[5], s[6]);
        const unsigned pre4 = hmax2u(s[4], pre5);
        const unsigned pre3 = hmax2u(s[3], pre4);
        const unsigned pre2 = hmax2u(s[2], pre3);
        const unsigned pre1 = hmax2u(s[1], pre2);
        const unsigned pre0 = hmax2u(s[0], pre1);
        const unsigned suf7  = hmax2u(s[6], s[7]);
        const unsigned suf8  = hmax2u(suf7, s[8]);
        const unsigned suf9  = hmax2u(suf8, s[9]);
        const unsigned suf10 = hmax2u(suf9, s[10]);
        const unsigned suf11 = hmax2u(suf10, s[11]);
        const unsigned suf12 = hmax2u(suf11, s[12]);
        unsigned* t = tb[c % 5];
        t[0] = pre0;
        t[1] = hmax2u(pre1, suf7);
        t[2] = hmax2u(pre2, suf8);
        t[3] = hmax2u(pre3, suf9);
        t[4] = hmax2u(pre4, suf10);
        t[5] = hmax2u(pre5, suf11);
        t[6] = suf12;

        if (c < 8) {
            #pragma unroll
            for (int i = 0; i < 6; i++) s[i] = s[i + 7];
            #pragma unroll
            for (int i = 6; i < 13; i++) {
                const int rr = rbase + 7 * (c + 1) + i;
                const int row = CLAMP ? min(max(rr, 0), H - 1) : rr;
                s[i] = base[row * 256 + col];
            }
        }

        if (c >= 4) {
            #pragma unroll
            for (int m = 0; m < 7; m++) {
                if (c < 8 || m < 4) {
                    unsigned v = tb[(c - 4) % 5][m];
                    v = hmax2u(v, tb[(c - 3) % 5][m]);
                    v = hmax2u(v, tb[(c - 2) % 5][m]);
                    v = hmax2u(v, tb[(c - 1) % 5][m]);
                    v = hmax2u(v, tb[c % 5][m]);
                    const float2 f = __half22float2(*reinterpret_cast<__half2*>(&v));
                    acc += f.x + f.y;           // dc >= 0, |.| is identity
                }
            }
        }
    }
    return acc;
}

// ---------------------------------------------------------------------------
// Kernel 2: vertical 35-tall max + mean. 1024 blocks x 128 threads.
// __launch_bounds__(128, 9): cap regs at 56 -> 9 blocks/SM (was 8 at 64 regs).
// ---------------------------------------------------------------------------
__global__ __launch_bounds__(128, 9) void vpass_kernel(float* __restrict__ out) {
    const int bx = blockIdx.x;
    const int n  = bx >> 5;
    const int st = (bx >> 1) & 15;
    const int cf = (bx & 1) << 7;
    const int tid = threadIdx.x;
    const int col = cf + tid;

    const unsigned* base = (const unsigned*)(g_hmax + (size_t)n * HW);
    const int rbase = (st << 5) - 17;

    const bool edge = (st == 0) || (st == 15);
    const float acc = edge ? vcol_scan<true>(base, rbase, col)
                           : vcol_scan<false>(base, rbase, col);

    // block reduction 128 -> 1
    __shared__ float red[4];
    const int lane = tid & 31;
    float a = acc;
    #pragma unroll
    for (int off = 16; off; off >>= 1)
        a += __shfl_down_sync(0xffffffffu, a, off);
    if (lane == 0) red[tid >> 5] = a;
    __syncthreads();
    if (tid < 4) {
        float v = red[tid];
        #pragma unroll
        for (int off = 2; off; off >>= 1)
            v += __shfl_down_sync(0xfu, v, off);
        if (tid == 0) g_partial[bx] = v;
    }

    // last block: deterministic final reduce + write
    __shared__ bool is_last;
    if (tid == 0) {
        __threadfence();
        is_last = (atomicAdd(&g_count, 1) == VBLK - 1);
    }
    __syncthreads();
    if (is_last) {
        __threadfence();
        float v = 0.0f;
        #pragma unroll
        for (int k = 0; k < 8; k++)
            v += g_partial[tid + 128 * k];
        #pragma unroll
        for (int off = 16; off; off >>= 1)
            v += __shfl_down_sync(0xffffffffu, v, off);
        if (lane == 0) red[tid >> 5] = v;
        __syncthreads();
        if (tid < 4) {
            float x = red[tid];
            #pragma unroll
            for (int off = 2; off; off >>= 1)
                x += __shfl_down_sync(0xfu, x, off);
            if (tid == 0) {
                out[0] = x * (1.0f / ((float)NIMG * (float)HW));
                g_count = 0;   // reset for graph replay
            }
        }
    }
}

// ---------------------------------------------------------------------------
extern "C" void kernel_launch(void* const* d_in, const int* in_sizes, int n_in,
                              void* d_out, int out_size) {
    const float* img = (const float*)d_in[0];
    float* out = (float*)d_out;

    hpass_kernel<<<NIMG * H, 128>>>(img);
    vpass_kernel<<<VBLK, 128>>>(out);
}

// round 17
// speedup vs baseline: 1.1393x; 1.1393x over previous
#include <cuda_runtime.h>
#include <cuda_fp16.h>
#include <float.h>

#define NIMG 32
#define H    512
#define W    512
#define HW   (H * W)
#define CHW  (3 * HW)

#define NEG2 0xFC00FC00u      // half2(-inf, -inf)

#define VBLK  (NIMG * 16 * 2)        // 1024 blocks: (img, 32-row strip, col half)

__device__ __half g_hmax[NIMG * HW]; // fp16 intermediate (16.75 MB, L2-resident)
__device__ float  g_partial[VBLK];
__device__ int    g_count;           // zero-init; reset by last block

__device__ __forceinline__ unsigned hmax2u(unsigned a, unsigned b) {
    __half2 ha = *reinterpret_cast<__half2*>(&a);
    __half2 hb = *reinterpret_cast<__half2*>(&b);
    __half2 hm = __hmax2(ha, hb);
    return *reinterpret_cast<unsigned*>(&hm);
}
__device__ __forceinline__ unsigned sh1(unsigned a, unsigned b) {
    return __byte_perm(a, b, 0x5432);   // (a.hi, b.lo)
}

// ---------------------------------------------------------------------------
// Kernel 1 — EXACT R13 version (measured best; ~17us, at LTS cap):
// c = 1 - min3(channels) -> fp16, horizontal 35-wide sliding max, packed half2.
// One block per (n,h) row, 128 threads.
// ---------------------------------------------------------------------------
__global__ __launch_bounds__(128) void hpass_kernel(const float* __restrict__ img) {
    const int row = blockIdx.x;
    const int n   = row >> 9;
    const int h   = row & (H - 1);
    const float* p = img + (size_t)n * CHW + (size_t)h * W;

    __shared__ unsigned s2[276];   // px -20 .. 531
    __shared__ unsigned t2[276];

    const int tid = threadIdx.x;

    if (tid < 20) s2[tid < 10 ? tid : 256 + tid] = NEG2;

    const float4 a = ((const float4*)p)[tid];
    const float4 b = ((const float4*)(p + HW))[tid];
    const float4 c = ((const float4*)(p + 2 * HW))[tid];
    float c0 = 1.0f - fminf(a.x, fminf(b.x, c.x));
    float c1 = 1.0f - fminf(a.y, fminf(b.y, c.y));
    float c2 = 1.0f - fminf(a.z, fminf(b.z, c.z));
    float c3 = 1.0f - fminf(a.w, fminf(b.w, c.w));
    __half2 h01 = __floats2half2_rn(c0, c1);
    __half2 h23 = __floats2half2_rn(c2, c3);
    s2[2 * tid + 10] = *reinterpret_cast<unsigned*>(&h01);
    s2[2 * tid + 11] = *reinterpret_cast<unsigned*>(&h23);
    __syncthreads();

    #pragma unroll
    for (int i = tid; i < 273; i += 128) {
        const unsigned A = s2[i], B = s2[i + 1], C = s2[i + 2];
        t2[i] = hmax2u(hmax2u(hmax2u(A, sh1(A, B)), hmax2u(B, sh1(B, C))), C);
    }
    __syncthreads();

    unsigned* orow = (unsigned*)(g_hmax + (size_t)row * W);
    #pragma unroll
    for (int q = tid; q < 256; q += 128) {
        unsigned v;
        v = sh1(t2[q + 1], t2[q + 2]);
        v = hmax2u(v, t2[q + 4]);
        v = hmax2u(v, sh1(t2[q + 6], t2[q + 7]));
        v = hmax2u(v, t2[q + 9]);
        v = hmax2u(v, sh1(t2[q + 11], t2[q + 12]));
        v = hmax2u(v, t2[q + 14]);
        v = hmax2u(v, sh1(t2[q + 16], t2[q + 17]));
        orow[q] = v;
    }
}

// ---------------------------------------------------------------------------
// Per-thread vertical 35-max column scan over a 32-row strip (R13 internals).
// width-35 = 5 taps (stride 7) over width-7 brick maxes; ring tb[5][7].
// Emission accumulates in packed half2 (1 HADD2/output instead of cvt+2 FADD);
// per-half-lane sum <= 32, safely in fp16 range. CLAMP=false for interior.
// ---------------------------------------------------------------------------
template <bool CLAMP>
__device__ __forceinline__ float vcol_scan(const unsigned* __restrict__ base,
                                           int rbase, int col) {
    unsigned s[13];
    unsigned tb[5][7];
    __half2 acc2 = __floats2half2_rn(0.0f, 0.0f);

    #pragma unroll
    for (int i = 0; i < 13; i++) {
        const int row = CLAMP ? min(max(rbase + i, 0), H - 1) : (rbase + i);
        s[i] = base[row * 256 + col];
    }

    #pragma unroll
    for (int c = 0; c < 9; c++) {
        const unsigned pre5 = hmax2u(s[5], s[6]);
        const unsigned pre4 = hmax2u(s[4], pre5);
        const unsigned pre3 = hmax2u(s[3], pre4);
        const unsigned pre2 = hmax2u(s[2], pre3);
        const unsigned pre1 = hmax2u(s[1], pre2);
        const unsigned pre0 = hmax2u(s[0], pre1);
        const unsigned suf7  = hmax2u(s[6], s[7]);
        const unsigned suf8  = hmax2u(suf7, s[8]);
        const unsigned suf9  = hmax2u(suf8, s[9]);
        const unsigned suf10 = hmax2u(suf9, s[10]);
        const unsigned suf11 = hmax2u(suf10, s[11]);
        const unsigned suf12 = hmax2u(suf11, s[12]);
        unsigned* t = tb[c % 5];
        t[0] = pre0;
        t[1] = hmax2u(pre1, suf7);
        t[2] = hmax2u(pre2, suf8);
        t[3] = hmax2u(pre3, suf9);
        t[4] = hmax2u(pre4, suf10);
        t[5] = hmax2u(pre5, suf11);
        t[6] = suf12;

        if (c < 8) {
            #pragma unroll
            for (int i = 0; i < 6; i++) s[i] = s[i + 7];
            #pragma unroll
            for (int i = 6; i < 13; i++) {
                const int rr = rbase + 7 * (c + 1) + i;
                const int row = CLAMP ? min(max(rr, 0), H - 1) : rr;
                s[i] = base[row * 256 + col];
            }
        }

        if (c >= 4) {
            #pragma unroll
            for (int m = 0; m < 7; m++) {
                if (c < 8 || m < 4) {
                    unsigned v = tb[(c - 4) % 5][m];
                    v = hmax2u(v, tb[(c - 3) % 5][m]);
                    v = hmax2u(v, tb[(c - 2) % 5][m]);
                    v = hmax2u(v, tb[(c - 1) % 5][m]);
                    v = hmax2u(v, tb[c % 5][m]);
                    acc2 = __hadd2(acc2, *reinterpret_cast<__half2*>(&v));
                }
            }
        }
    }
    const float2 f = __half22float2(acc2);
    return f.x + f.y;
}

// ---------------------------------------------------------------------------
// Kernel 2: vertical 35-tall max + mean. 1024 blocks x 128 threads.
// (No occupancy override — 64 regs / 8 blocks/SM is the measured optimum.)
// ---------------------------------------------------------------------------
__global__ __launch_bounds__(128) void vpass_kernel(float* __restrict__ out) {
    const int bx = blockIdx.x;
    const int n  = bx >> 5;
    const int st = (bx >> 1) & 15;
    const int cf = (bx & 1) << 7;
    const int tid = threadIdx.x;
    const int col = cf + tid;

    const unsigned* base = (const unsigned*)(g_hmax + (size_t)n * HW);
    const int rbase = (st << 5) - 17;

    const bool edge = (st == 0) || (st == 15);
    const float acc = edge ? vcol_scan<true>(base, rbase, col)
                           : vcol_scan<false>(base, rbase, col);

    // block reduction 128 -> 1
    __shared__ float red[4];
    const int lane = tid & 31;
    float a = acc;
    #pragma unroll
    for (int off = 16; off; off >>= 1)
        a += __shfl_down_sync(0xffffffffu, a, off);
    if (lane == 0) red[tid >> 5] = a;
    __syncthreads();
    if (tid < 4) {
        float v = red[tid];
        #pragma unroll
        for (int off = 2; off; off >>= 1)
            v += __shfl_down_sync(0xfu, v, off);
        if (tid == 0) g_partial[bx] = v;
    }

    // last block: deterministic final reduce + write
    __shared__ bool is_last;
    if (tid == 0) {
        __threadfence();
        is_last = (atomicAdd(&g_count, 1) == VBLK - 1);
    }
    __syncthreads();
    if (is_last) {
        __threadfence();
        float v = 0.0f;
        #pragma unroll
        for (int k = 0; k < 8; k++)
            v += g_partial[tid + 128 * k];
        #pragma unroll
        for (int off = 16; off; off >>= 1)
            v += __shfl_down_sync(0xffffffffu, v, off);
        if (lane == 0) red[tid >> 5] = v;
        __syncthreads();
        if (tid < 4) {
            float x = red[tid];
            #pragma unroll
            for (int off = 2; off; off >>= 1)
                x += __shfl_down_sync(0xfu, x, off);
            if (tid == 0) {
                out[0] = x * (1.0f / ((float)NIMG * (float)HW));
                g_count = 0;   // reset for graph replay
            }
        }
    }
}

// ---------------------------------------------------------------------------
extern "C" void kernel_launch(void* const* d_in, const int* in_sizes, int n_in,
                              void* d_out, int out_size) {
    const float* img = (const float*)d_in[0];
    float* out = (float*)d_out;

    hpass_kernel<<<NIMG * H, 128>>>(img);
    vpass_kernel<<<VBLK, 128>>>(out);
}